// round 16
// baseline (speedup 1.0000x reference)
#include <cuda_runtime.h>

#define N_  256
#define P_  5
#define H_  32
#define B_  256
#define K_  1280
#define THRESH_ 0.01f

#define SPLITK 8
#define KZ  160             // K per z-block (2 rounds of 80)
#define KC  80
#define JZ  32              // j per z-block
#define ITI 32              // i tile
#define BTI 64              // b tile
#define PITCH 84            // row pitch for As/Bs (16B-aligned rows)

__device__ float g_part[SPLITK][B_ * N_];
__device__ int   g_ticket[32];   // per (i-tile, b-tile), zero-init

#define FMA_F32X2(d, a, b) \
    asm("fma.rn.f32x2 %0, %1, %2, %0;" : "+l"(d) : "l"(a), "l"(b))

struct __align__(16) GemmSmem {
    float As[BTI][PITCH];   // [b][k] row-major, 80 k used
    float Bs[ITI][PITCH];   // [i][k] row-major
};
struct __align__(16) EpiSmem {
    float w1s[H_][ITI + 1];
    float b1s[H_][ITI + 1];
    float w2m[H_][ITI + 1];
    float w2s[H_][ITI + 1];
    float b2m[ITI];
    float b2sd[ITI];
};

__global__ __launch_bounds__(256)
void fused_kernel(const float* __restrict__ x,
                  const float* __restrict__ adj,
                  const float* __restrict__ bp,
                  const float* __restrict__ w_pw,
                  const float* __restrict__ b_pw,
                  const float* __restrict__ W1,
                  const float* __restrict__ b1,
                  const float* __restrict__ W2,
                  const float* __restrict__ b2,
                  float* __restrict__ out)
{
    __shared__ union { GemmSmem g; EpiSmem e; } U;
    __shared__ float adj_s[JZ][ITI + 1];
    __shared__ float bp_s[KZ];
    __shared__ float bsum[8][ITI];
    __shared__ int s_last;

    const int tid = threadIdx.x;
    const int i0  = blockIdx.x * ITI;
    const int b0  = blockIdx.y * BTI;
    const int z   = blockIdx.z;
    const int j0z = z * JZ;

    // ---- stage bp (160) + masked adj chunk (32 j x 32 i) ----
    if (tid < KZ) bp_s[tid] = bp[j0z * P_ + tid];
    {
        const int j  = tid >> 3;           // 0..31
        const int i4 = (tid & 7) * 4;      // 0..28
        float4 e = *reinterpret_cast<const float4*>(adj + (size_t)(j0z + j) * N_ + i0 + i4);
        const int gj = j0z + j;
        adj_s[j][i4 + 0] = (e.x > THRESH_ && (i0 + i4 + 0) != gj) ? e.x : 0.f;
        adj_s[j][i4 + 1] = (e.y > THRESH_ && (i0 + i4 + 1) != gj) ? e.y : 0.f;
        adj_s[j][i4 + 2] = (e.z > THRESH_ && (i0 + i4 + 2) != gj) ? e.z : 0.f;
        adj_s[j][i4 + 3] = (e.w > THRESH_ && (i0 + i4 + 3) != gj) ? e.w : 0.f;
    }
    // ---- bias chunk partials (over this z's 32 j) ----
    __syncthreads();
    {
        const int il = tid & 31;
        const int q  = tid >> 5;           // 0..7 -> 4 j each
        float4 bpv = *reinterpret_cast<const float4*>(
            b_pw + (size_t)(i0 + il) * N_ + j0z + q * 4);
        float s = adj_s[q * 4 + 0][il] * bpv.x;
        s = fmaf(adj_s[q * 4 + 1][il], bpv.y, s);
        s = fmaf(adj_s[q * 4 + 2][il], bpv.z, s);
        s = fmaf(adj_s[q * 4 + 3][il], bpv.w, s);
        bsum[q][il] = s;
    }

    const int tx = tid & 7;                // i: tx + 8v
    const int ty = tid >> 3;               // b: ty, ty+32
    unsigned long long acc2[2][4] = {};    // [u(b)][v(i)] = (sum even k, sum odd k)

    #pragma unroll
    for (int round = 0; round < 2; ++round) {
        const int kz0 = z * KZ + round * KC;   // global k base
        __syncthreads();
        // ---- Bs fill: row-major, coalesced loads+stores ----
        #pragma unroll
        for (int it = 0; it < 3; ++it) {
            const int t = tid + it * 256;
            if (t < ITI * 20) {
                const int row = t / 20;
                const int c4  = t % 20;
                const int k0  = c4 * 4;
                float4 w = *reinterpret_cast<const float4*>(
                    w_pw + (size_t)(i0 + row) * K_ + kz0 + k0);
                w.x *= adj_s[round * 16 + (k0 + 0) / P_][row];
                w.y *= adj_s[round * 16 + (k0 + 1) / P_][row];
                w.z *= adj_s[round * 16 + (k0 + 2) / P_][row];
                w.w *= adj_s[round * 16 + (k0 + 3) / P_][row];
                *reinterpret_cast<float4*>(&U.g.Bs[row][k0]) = w;
            }
        }
        // ---- As fill: row-major act ----
        {
            const int r = tid & 63;        // b-local
            const int q = tid >> 6;        // 0..3 -> 4 j each
            float4 xv = *reinterpret_cast<const float4*>(
                x + (size_t)(b0 + r) * N_ + j0z + round * 16 + q * 4);
            float xl[4] = {xv.x, xv.y, xv.z, xv.w};
            #pragma unroll
            for (int jj = 0; jj < 4; ++jj) {
                const int kb = (q * 4 + jj) * P_;
                #pragma unroll
                for (int p = 0; p < P_; ++p)
                    U.g.As[r][kb + p] = fmaxf(xl[jj] - bp_s[round * KC + kb + p], 0.f);
            }
        }
        __syncthreads();

        // ---- main loop: k-packed FMA2, no PACK instructions ----
        #pragma unroll 5
        for (int kk = 0; kk < KC / 4; ++kk) {
            ulonglong2 av[2], bv[4];
            av[0] = *reinterpret_cast<const ulonglong2*>(&U.g.As[ty     ][kk * 4]);
            av[1] = *reinterpret_cast<const ulonglong2*>(&U.g.As[ty + 32][kk * 4]);
            #pragma unroll
            for (int v = 0; v < 4; ++v)
                bv[v] = *reinterpret_cast<const ulonglong2*>(&U.g.Bs[tx + 8 * v][kk * 4]);
            #pragma unroll
            for (int u = 0; u < 2; ++u)
                #pragma unroll
                for (int v = 0; v < 4; ++v) {
                    FMA_F32X2(acc2[u][v], av[u].x, bv[v].x);
                    FMA_F32X2(acc2[u][v], av[u].y, bv[v].y);
                }
        }
    }

    // ---- unpack (even+odd), add bias chunk, store partials once ----
    {
        float* dst = g_part[z];
        #pragma unroll
        for (int u = 0; u < 2; ++u) {
            const int b = b0 + ty + u * 32;
            #pragma unroll
            for (int v = 0; v < 4; ++v) {
                const int il = tx + 8 * v;
                float bsv = bsum[0][il] + bsum[1][il] + bsum[2][il] + bsum[3][il]
                          + bsum[4][il] + bsum[5][il] + bsum[6][il] + bsum[7][il];
                unsigned int lo, hi;
                asm("mov.b64 {%0, %1}, %2;" : "=r"(lo), "=r"(hi) : "l"(acc2[u][v]));
                dst[(size_t)b * N_ + i0 + il] =
                    __uint_as_float(lo) + __uint_as_float(hi) + bsv;
            }
        }
    }

    // ---- ticket: last z-block of this tile runs the MLP epilogue ----
    __threadfence();
    __syncthreads();
    if (tid == 0) {
        const int t = blockIdx.x * 4 + blockIdx.y;
        int tk = atomicAdd(&g_ticket[t], 1);
        s_last = (tk == SPLITK - 1);
        if (s_last) atomicExch(&g_ticket[t], 0);   // reset for graph replay
    }
    __syncthreads();
    if (!s_last) return;
    __threadfence();

    // ================= epilogue (32 reducer blocks chip-wide) =================
    {
        const int k  = tid & 31;
        const int ig = tid >> 5;           // 0..7
        #pragma unroll
        for (int r = 0; r < 4; ++r) {
            const int i = ig + r * 8;
            U.e.w1s[k][i] = W1[(size_t)(i0 + i) * H_ + k];
            U.e.b1s[k][i] = b1[(size_t)(i0 + i) * H_ + k];
        }
        const int o  = tid & 63;
        const int iw = tid >> 6;           // 0..3
        #pragma unroll
        for (int r = 0; r < 8; ++r) {
            const int i = iw + r * 4;
            float v = W2[(size_t)(i0 + i) * 2 * H_ + o];
            if (o < H_) U.e.w2m[o][i] = v;
            else        U.e.w2s[o - H_][i] = v;
        }
        if (tid < 2 * ITI) {
            const int i = tid >> 1;
            if (tid & 1) U.e.b2sd[i] = b2[(i0 + i) * 2 + 1];
            else         U.e.b2m[i]  = b2[(i0 + i) * 2 + 0];
        }
    }
    __syncthreads();

    const int iq = tid & 7;                // i quad: i0 + iq*4 + v
    const int bb = tid >> 3;               // 0..31 -> b = b0+bb, b0+bb+32

    #pragma unroll
    for (int u = 0; u < 2; ++u) {
        const int b = b0 + bb + u * 32;
        float4 c4 = make_float4(0.f, 0.f, 0.f, 0.f);
        #pragma unroll
        for (int zz = 0; zz < SPLITK; ++zz) {
            float4 p = *reinterpret_cast<const float4*>(
                &g_part[zz][(size_t)b * N_ + i0 + iq * 4]);
            c4.x += p.x; c4.y += p.y; c4.z += p.z; c4.w += p.w;
        }
        float cv[4] = {c4.x, c4.y, c4.z, c4.w};
        #pragma unroll
        for (int v = 0; v < 4; ++v) {
            const int il = iq * 4 + v;
            float m  = U.e.b2m[il];
            float sd = U.e.b2sd[il];
            #pragma unroll 4
            for (int k = 0; k < H_; ++k) {
                float h = fmaxf(fmaf(cv[v], U.e.w1s[k][il], U.e.b1s[k][il]), 0.f);
                m  = fmaf(U.e.w2m[k][il], h, m);
                sd = fmaf(U.e.w2s[k][il], h, sd);
            }
            out[(size_t)b * N_ + i0 + il]        = m;
            out[(size_t)(B_ + b) * N_ + i0 + il] = sd;
        }
    }
}

extern "C" void kernel_launch(void* const* d_in, const int* in_sizes, int n_in,
                              void* d_out, int out_size)
{
    const float* x    = (const float*)d_in[0];
    const float* adj  = (const float*)d_in[1];
    const float* bp   = (const float*)d_in[2];
    const float* w_pw = (const float*)d_in[3];
    const float* b_pw = (const float*)d_in[4];
    const float* W1   = (const float*)d_in[5];
    const float* b1   = (const float*)d_in[6];
    const float* W2   = (const float*)d_in[7];
    const float* b2   = (const float*)d_in[8];
    float* out = (float*)d_out;

    fused_kernel<<<dim3(N_ / ITI, B_ / BTI, SPLITK), 256>>>(
        x, adj, bp, w_pw, b_pw, W1, b1, W2, b2, out);
}

// round 17
// speedup vs baseline: 1.3378x; 1.3378x over previous
#include <cuda_runtime.h>

#define N_  256
#define P_  5
#define H_  32
#define B_  256
#define K_  1280            // N_*P_
#define THRESH_ 0.01f

#define SPLITK 8
#define KC 80               // K per round = 16 j exactly
#define JC 16               // j per round
#define BSP 68              // padded Bs row (rows stay 16B aligned)

// ---- scratch ----
__device__ float g_part[SPLITK][B_ * N_]; // split-K partials [z][b][i]

#define FMA_F32X2(d, a, b) \
    asm("fma.rn.f32x2 %0, %1, %2, %0;" : "+l"(d) : "l"(a), "l"(b))

#define PACK_DUP(d, s) \
    asm("mov.b64 %0, {%1, %1};" : "=l"(d) : "r"(__float_as_uint(s)))

// ---------------------------------------------------------------
// GEMM (R10 pipeline, two K-rounds per block).
// grid = (4 i-tiles, 4 b-tiles, 8 k-chunks) = 128 blocks, 256 thr.
// ---------------------------------------------------------------
__global__ __launch_bounds__(256)
void gemm_fused(const float* __restrict__ x,
                const float* __restrict__ adj,
                const float* __restrict__ bp,
                const float* __restrict__ w_pw,
                const float* __restrict__ b_pw)
{
    __shared__ __align__(16) float As[KC][64];    // act:  [k][b]
    __shared__ __align__(16) float Bs[KC][BSP];   // effw: [k][i]
    __shared__ float adj_s[JC][64];               // masked adjacency.T chunk [j][i]
    __shared__ float bp_s[KC];
    __shared__ float bsum[4][64];                 // bias partials (both rounds)

    const int tid = threadIdx.x;
    const int i0  = blockIdx.x * 64;
    const int b0  = blockIdx.y * 64;

    const int tx = tid & 15;   // i direction
    const int ty = tid >> 4;   // b direction
    unsigned long long acc2[4][2] = {};
    float bias_acc = 0.f;      // this thread's (q,il) bias partial, both rounds

    #pragma unroll
    for (int round = 0; round < 2; ++round) {
        const int j0  = (blockIdx.z * 2 + round) * JC;
        const int kc0 = j0 * P_;

        __syncthreads();   // protect previous round's As/Bs/adj_s from overwrite

        // ---- stage bp chunk + masked adj chunk ----
        if (tid < KC) bp_s[tid] = bp[kc0 + tid];
        {
            const int j  = tid >> 4;          // 0..15
            const int i4 = (tid & 15) * 4;
            float4 e = *reinterpret_cast<const float4*>(
                adj + (size_t)(j0 + j) * N_ + i0 + i4);
            const int gj = j0 + j;
            adj_s[j][i4 + 0] = (e.x > THRESH_ && (i0 + i4 + 0) != gj) ? e.x : 0.f;
            adj_s[j][i4 + 1] = (e.y > THRESH_ && (i0 + i4 + 1) != gj) ? e.y : 0.f;
            adj_s[j][i4 + 2] = (e.z > THRESH_ && (i0 + i4 + 2) != gj) ? e.z : 0.f;
            adj_s[j][i4 + 3] = (e.w > THRESH_ && (i0 + i4 + 3) != gj) ? e.w : 0.f;
        }
        __syncthreads();

        // ---- generate effw tile: Bs[k][i] = adj_s[j(k)][i] * w_pw[i][k] ----
        {
            const int r = tid >> 2;           // i-local 0..63
            const int q = tid & 3;
            #pragma unroll
            for (int c = 0; c < 5; ++c) {
                const int kq = c * 16 + q * 4;
                float4 w = *reinterpret_cast<const float4*>(
                    w_pw + (size_t)(i0 + r) * K_ + kc0 + kq);
                Bs[kq + 0][r] = adj_s[(kq + 0) / P_][r] * w.x;
                Bs[kq + 1][r] = adj_s[(kq + 1) / P_][r] * w.y;
                Bs[kq + 2][r] = adj_s[(kq + 2) / P_][r] * w.z;
                Bs[kq + 3][r] = adj_s[(kq + 3) / P_][r] * w.w;
            }
        }
        // ---- generate act tile: As[k][b] = relu(x[b, j(k)] - bp[k]) ----
        {
            const int r = tid & 63;           // b-local
            const int q = tid >> 6;           // 0..3 -> 4 j each
            float4 xv = *reinterpret_cast<const float4*>(
                x + (size_t)(b0 + r) * N_ + j0 + q * 4);
            float xl[4] = {xv.x, xv.y, xv.z, xv.w};
            #pragma unroll
            for (int jj = 0; jj < 4; ++jj) {
                const float xj = xl[jj];
                const int jl = q * 4 + jj;
                #pragma unroll
                for (int p = 0; p < P_; ++p) {
                    const int k = jl * P_ + p;
                    As[k][r] = fmaxf(xj - bp_s[k], 0.f);
                }
            }
        }
        // ---- bias partials for this round (accumulate in register) ----
        {
            const int il = tid & 63;
            const int q  = tid >> 6;
            float4 bpv = *reinterpret_cast<const float4*>(
                b_pw + (size_t)(i0 + il) * N_ + j0 + q * 4);
            float s = adj_s[q * 4 + 0][il] * bpv.x;
            s = fmaf(adj_s[q * 4 + 1][il], bpv.y, s);
            s = fmaf(adj_s[q * 4 + 2][il], bpv.z, s);
            s = fmaf(adj_s[q * 4 + 3][il], bpv.w, s);
            bias_acc += s;
        }
        __syncthreads();

        // ---- main loop: 4x4 tile via 8 FMA2 per k ----
        #pragma unroll 8
        for (int k = 0; k < KC; ++k) {
            float4 a4 = *reinterpret_cast<const float4*>(&As[k][ty * 4]);
            ulonglong2 bv = *reinterpret_cast<const ulonglong2*>(&Bs[k][tx * 4]);
            unsigned long long a0, a1, a2, a3;
            PACK_DUP(a0, a4.x);
            PACK_DUP(a1, a4.y);
            PACK_DUP(a2, a4.z);
            PACK_DUP(a3, a4.w);
            FMA_F32X2(acc2[0][0], a0, bv.x); FMA_F32X2(acc2[0][1], a0, bv.y);
            FMA_F32X2(acc2[1][0], a1, bv.x); FMA_F32X2(acc2[1][1], a1, bv.y);
            FMA_F32X2(acc2[2][0], a2, bv.x); FMA_F32X2(acc2[2][1], a2, bv.y);
            FMA_F32X2(acc2[3][0], a3, bv.x); FMA_F32X2(acc2[3][1], a3, bv.y);
        }
    }

    // ---- publish bias partials, then unpack + store ----
    bsum[tid >> 6][tid & 63] = bias_acc;
    __syncthreads();

    float bs0 = bsum[0][tx*4+0] + bsum[1][tx*4+0] + bsum[2][tx*4+0] + bsum[3][tx*4+0];
    float bs1 = bsum[0][tx*4+1] + bsum[1][tx*4+1] + bsum[2][tx*4+1] + bsum[3][tx*4+1];
    float bs2 = bsum[0][tx*4+2] + bsum[1][tx*4+2] + bsum[2][tx*4+2] + bsum[3][tx*4+2];
    float bs3 = bsum[0][tx*4+3] + bsum[1][tx*4+3] + bsum[2][tx*4+3] + bsum[3][tx*4+3];

    float* dst = g_part[blockIdx.z];
    #pragma unroll
    for (int u = 0; u < 4; ++u) {
        unsigned int c0, c1, c2, c3;
        asm("mov.b64 {%0, %1}, %2;" : "=r"(c0), "=r"(c1) : "l"(acc2[u][0]));
        asm("mov.b64 {%0, %1}, %2;" : "=r"(c2), "=r"(c3) : "l"(acc2[u][1]));
        float4 v = make_float4(__uint_as_float(c0) + bs0,
                               __uint_as_float(c1) + bs1,
                               __uint_as_float(c2) + bs2,
                               __uint_as_float(c3) + bs3);
        *reinterpret_cast<float4*>(&dst[(size_t)(b0 + ty*4 + u) * N_ + i0 + tx*4]) = v;
    }
}

// ---------------------------------------------------------------
// epilogue (R10-exact, SPLITK=8): grid = (8, 32), 256 thr.
// ---------------------------------------------------------------
#define EIT 32
#define EBT 8

__global__ __launch_bounds__(256)
void epi_kernel(const float* __restrict__ W1,
                const float* __restrict__ b1,
                const float* __restrict__ W2,
                const float* __restrict__ b2,
                float* __restrict__ out)
{
    __shared__ float w1s[H_][EIT + 1];
    __shared__ float b1s[H_][EIT + 1];
    __shared__ float w2m[H_][EIT + 1];
    __shared__ float w2s[H_][EIT + 1];
    __shared__ float b2s[2][EIT];

    const int tid = threadIdx.x;
    const int i0  = blockIdx.x * EIT;
    const int b0  = blockIdx.y * EBT;

    {
        const int il = tid >> 5;
        const int k  = tid & 31;
        #pragma unroll
        for (int r = 0; r < 4; ++r) {
            const int i = il + r * 8;
            w1s[k][i] = W1[(i0 + i) * H_ + k];
            b1s[k][i] = b1[(i0 + i) * H_ + k];
        }
        const int il2 = tid >> 6;
        const int o   = tid & 63;
        #pragma unroll
        for (int r = 0; r < 8; ++r) {
            const int i = il2 + r * 4;
            float v = W2[(i0 + i) * 2 * H_ + o];
            if (o < H_) w2m[o][i] = v;
            else        w2s[o - H_][i] = v;
        }
        if (tid < 2 * EIT) {
            const int i = tid >> 1;
            b2s[tid & 1][i] = b2[(i0 + i) * 2 + (tid & 1)];
        }
    }
    __syncthreads();

    const int il = tid & 31;
    const int bq = tid >> 5;
    const int gi = i0 + il;
    const int b  = b0 + bq;

    float c = 0.f;
    #pragma unroll
    for (int s = 0; s < SPLITK; ++s)
        c += g_part[s][(size_t)b * N_ + gi];

    float m  = b2s[0][il];
    float sd = b2s[1][il];
    #pragma unroll
    for (int k = 0; k < H_; ++k) {
        float h = fmaxf(fmaf(c, w1s[k][il], b1s[k][il]), 0.f);
        m  = fmaf(w2m[k][il], h, m);
        sd = fmaf(w2s[k][il], h, sd);
    }
    out[(size_t)b * N_ + gi]        = m;
    out[(size_t)(B_ + b) * N_ + gi] = sd;
}

extern "C" void kernel_launch(void* const* d_in, const int* in_sizes, int n_in,
                              void* d_out, int out_size)
{
    const float* x    = (const float*)d_in[0];
    const float* adj  = (const float*)d_in[1];
    const float* bp   = (const float*)d_in[2];
    const float* w_pw = (const float*)d_in[3];
    const float* b_pw = (const float*)d_in[4];
    const float* W1   = (const float*)d_in[5];
    const float* b1   = (const float*)d_in[6];
    const float* W2   = (const float*)d_in[7];
    const float* b2   = (const float*)d_in[8];
    float* out = (float*)d_out;

    gemm_fused<<<dim3(4, 4, SPLITK), 256>>>(x, adj, bp, w_pw, b_pw);
    epi_kernel<<<dim3(N_ / EIT, B_ / EBT), 256>>>(W1, b1, W2, b2, out);
}